// round 3
// baseline (speedup 1.0000x reference)
#include <cuda_runtime.h>

#define BH      32
#define D       16
#define DV      64
#define CS      256
#define NC      16
#define NCHUNK  512
#define NPAIR   136

// state layout (floats) per chunk
#define OFF_KSUM  0
#define OFF_K2    16
#define OFF_VSUM  152
#define OFF_KVLIN 216
#define OFF_KVQ   1240
#define S_FLOATS  9944   // 16 + 136 + 64 + 1024 + 8704

__device__ __align__(16) float g_state[(size_t)NCHUNK * S_FLOATS];

__device__ __forceinline__ void fma4(float4& a, float c, const float4 v) {
    a.x = fmaf(c, v.x, a.x);
    a.y = fmaf(c, v.y, a.y);
    a.z = fmaf(c, v.z, a.z);
    a.w = fmaf(c, v.w, a.w);
}

// ---------------------------------------------------------------------------
// Pass 1: per-chunk states.  512 CTAs x 256 threads.
// ---------------------------------------------------------------------------
__global__ __launch_bounds__(256) void build_kernel(const float* __restrict__ kg,
                                                    const float* __restrict__ vg) {
    extern __shared__ float smem[];
    float* sv = smem;               // CS*DV floats
    float* sk = smem + CS * DV;     // CS*D floats
    const int cg  = blockIdx.x;
    const int tid = threadIdx.x;

    float4* sv4 = (float4*)sv;
    float4* sk4 = (float4*)sk;
    const float4* gv4 = (const float4*)(vg + (size_t)cg * CS * DV);
    const float4* gk4 = (const float4*)(kg + (size_t)cg * CS * D);
#pragma unroll
    for (int i = 0; i < 16; ++i) sv4[tid + 256 * i] = gv4[tid + 256 * i];
#pragma unroll
    for (int i = 0; i < 4; ++i)  sk4[tid + 256 * i] = gk4[tid + 256 * i];
    __syncthreads();

    float* st = g_state + (size_t)cg * S_FLOATS;

    if (tid < NPAIR) {
        // pair (d,e), d<=e, enumerated (0,0..15),(1,1..15),...
        int d = 0, pp = tid;
        while (pp >= D - d) { pp -= (D - d); ++d; }
        const int e = d + pp;
        const float w = (e == d) ? 0.5f : 1.0f;   // fold the 0.5 quad factor here

        float4 acc[16];
#pragma unroll
        for (int f = 0; f < 16; ++f) acc[f] = make_float4(0.f, 0.f, 0.f, 0.f);
        float acc2 = 0.f;

        for (int c = 0; c < CS; ++c) {
            const float coeff = sk[c * D + d] * sk[c * D + e];
            acc2 += coeff;
            const float4* vr = sv4 + c * 16;
#pragma unroll
            for (int f = 0; f < 16; ++f) fma4(acc[f], coeff, vr[f]);
        }

        float4* dst = (float4*)(st + OFF_KVQ + tid * DV);
#pragma unroll
        for (int f = 0; f < 16; ++f) {
            acc[f].x *= w; acc[f].y *= w; acc[f].z *= w; acc[f].w *= w;
            dst[f] = acc[f];
        }
        st[OFF_K2 + tid] = acc2 * w;
    } else {
        const int t = tid - NPAIR;    // 0..119
        for (int idx = t; idx < D * DV; idx += 256 - NPAIR) {
            const int d = idx >> 6, f = idx & 63;
            float a = 0.f;
            for (int c = 0; c < CS; ++c) a = fmaf(sk[c * D + d], sv[c * DV + f], a);
            st[OFF_KVLIN + idx] = a;
        }
        if (t < D) {
            float a = 0.f;
            for (int c = 0; c < CS; ++c) a += sk[c * D + t];
            st[OFF_KSUM + t] = a;
        } else if (t < D + DV) {
            const int f = t - D;
            float a = 0.f;
            for (int c = 0; c < CS; ++c) a += sv[c * DV + f];
            st[OFF_VSUM + f] = a;
        }
    }
}

// ---------------------------------------------------------------------------
// Pass 2: in-place EXCLUSIVE prefix over the 16 chunks of each (b,h).
// grid (32, 4) x 256 threads; MLP=16 per element.
// ---------------------------------------------------------------------------
__global__ void prefix_kernel() {
    const int bh = blockIdx.x;
    const int stride = gridDim.y * blockDim.x;
    for (int i = blockIdx.y * blockDim.x + threadIdx.x; i < S_FLOATS; i += stride) {
        float* p = g_state + (size_t)bh * NC * S_FLOATS + i;
        float vals[NC];
#pragma unroll
        for (int c = 0; c < NC; ++c) vals[c] = p[(size_t)c * S_FLOATS];
        float run = 0.f;
#pragma unroll
        for (int c = 0; c < NC; ++c) {
            const float t = vals[c];
            p[(size_t)c * S_FLOATS] = run;
            run += t;
        }
    }
}

// ---------------------------------------------------------------------------
// Pass 3: intra-chunk phi-attention + apply exclusive state, divide by z.
// 512 CTAs x 256 threads (thread = query row).
// ---------------------------------------------------------------------------
__global__ __launch_bounds__(256) void main_kernel(const float* __restrict__ qg,
                                                   const float* __restrict__ kg,
                                                   const float* __restrict__ vg,
                                                   float* __restrict__ outg) {
    extern __shared__ float smem[];
    float* sv     = smem;                 // CS*DV   = 16384 f
    float* sstate = sv + CS * DV;         // S_FLOATS=  9944 f
    float* sk     = sstate + S_FLOATS;    // CS*D    =  4096 f
    float* qs     = sk + CS * D;          // CS*17   =  4352 f (padded, thread-private rows)
    const int cg  = blockIdx.x;
    const int nc  = cg & (NC - 1);
    const int tid = threadIdx.x;

    float4* sv4 = (float4*)sv;
    float4* sk4 = (float4*)sk;
    float4* ss4 = (float4*)sstate;
    const float4* gv4 = (const float4*)(vg + (size_t)cg * CS * DV);
    const float4* gk4 = (const float4*)(kg + (size_t)cg * CS * D);
    const float4* gs4 = (const float4*)(g_state + (size_t)cg * S_FLOATS);
#pragma unroll
    for (int i = 0; i < 16; ++i) sv4[tid + 256 * i] = gv4[tid + 256 * i];
#pragma unroll
    for (int i = 0; i < 4; ++i)  sk4[tid + 256 * i] = gk4[tid + 256 * i];
    for (int i = tid; i < S_FLOATS / 4; i += 256) ss4[i] = gs4[i];

    float qreg[16];
    {
        const float4* gq4 = (const float4*)(qg + (size_t)cg * CS * D + (size_t)tid * D);
#pragma unroll
        for (int i = 0; i < 4; ++i) {
            float4 t = gq4[i];                      // q * d^-0.5
            qreg[4 * i + 0] = 0.25f * t.x;
            qreg[4 * i + 1] = 0.25f * t.y;
            qreg[4 * i + 2] = 0.25f * t.z;
            qreg[4 * i + 3] = 0.25f * t.w;
        }
        float* qrow = qs + tid * 17;
#pragma unroll
        for (int i = 0; i < 16; ++i) qrow[i] = qreg[i];
    }
    __syncthreads();

    float4 o4[16];
#pragma unroll
    for (int f = 0; f < 16; ++f) o4[f] = make_float4(0.f, 0.f, 0.f, 0.f);
    float z = 0.f;

    // ---- intra-chunk causal phi-attention (triangular per warp) ----
    const int c    = tid;
    const int jmax = ((c >> 5) + 1) << 5;
#pragma unroll 2
    for (int j = 0; j < jmax; ++j) {
        const float4* kr = sk4 + j * 4;
        float s0 = 0.f, s1 = 0.f;
        {
            float4 kk = kr[0];
            s0 = fmaf(qreg[0], kk.x, s0); s0 = fmaf(qreg[1], kk.y, s0);
            s0 = fmaf(qreg[2], kk.z, s0); s0 = fmaf(qreg[3], kk.w, s0);
            kk = kr[1];
            s0 = fmaf(qreg[4], kk.x, s0); s0 = fmaf(qreg[5], kk.y, s0);
            s0 = fmaf(qreg[6], kk.z, s0); s0 = fmaf(qreg[7], kk.w, s0);
            kk = kr[2];
            s1 = fmaf(qreg[8], kk.x, s1); s1 = fmaf(qreg[9], kk.y, s1);
            s1 = fmaf(qreg[10], kk.z, s1); s1 = fmaf(qreg[11], kk.w, s1);
            kk = kr[3];
            s1 = fmaf(qreg[12], kk.x, s1); s1 = fmaf(qreg[13], kk.y, s1);
            s1 = fmaf(qreg[14], kk.z, s1); s1 = fmaf(qreg[15], kk.w, s1);
        }
        const float s = s0 + s1;
        float phi = fmaf(0.5f * s, s, s) + 1.0f;   // 1 + s + 0.5 s^2
        phi = (j <= c) ? phi : 0.f;
        z += phi;
        const float4* vr = sv4 + j * 16;
#pragma unroll
        for (int f = 0; f < 16; ++f) fma4(o4[f], phi, vr[f]);
    }

    // ---- inter-chunk quadratic state (136 symmetric pairs, pre-weighted) ----
    {
        const float*  sk2 = sstate + OFF_K2;
        const float4* kvq = (const float4*)(sstate + OFF_KVQ);
        const float*  qrow = qs + c * 17;
        int d = 0, e = 0;
#pragma unroll 2
        for (int p = 0; p < NPAIR; ++p) {
            const float coeff = qrow[d] * qrow[e];
            z = fmaf(coeff, sk2[p], z);
            const float4* r = kvq + p * 16;
#pragma unroll
            for (int f = 0; f < 16; ++f) fma4(o4[f], coeff, r[f]);
            if (++e == D) { ++d; e = d; }
        }
    }

    // ---- inter-chunk linear state ----
    {
        const float*  ksum = sstate + OFF_KSUM;
        const float4* kvl  = (const float4*)(sstate + OFF_KVLIN);
#pragma unroll
        for (int d2 = 0; d2 < D; ++d2) {
            const float qd = qreg[d2];
            z = fmaf(qd, ksum[d2], z);
            const float4* r = kvl + d2 * 16;
#pragma unroll
            for (int f = 0; f < 16; ++f) fma4(o4[f], qd, r[f]);
        }
    }

    // ---- zeroth-order inter terms + normalize ----
    z += (float)(nc * CS);
    const float inv = 1.0f / (z + 1e-6f);
    const float4* vsum4 = (const float4*)(sstate + OFF_VSUM);
    float4* out4 = (float4*)(outg + (size_t)cg * CS * DV + (size_t)c * DV);
#pragma unroll
    for (int f = 0; f < 16; ++f) {
        const float4 vs = vsum4[f];
        float4 r;
        r.x = (o4[f].x + vs.x) * inv;
        r.y = (o4[f].y + vs.y) * inv;
        r.z = (o4[f].z + vs.z) * inv;
        r.w = (o4[f].w + vs.w) * inv;
        out4[f] = r;
    }
}

// ---------------------------------------------------------------------------
extern "C" void kernel_launch(void* const* d_in, const int* in_sizes, int n_in,
                              void* d_out, int out_size) {
    (void)in_sizes; (void)n_in; (void)out_size;
    const float* q = (const float*)d_in[0];
    const float* k = (const float*)d_in[1];
    const float* v = (const float*)d_in[2];
    float* out = (float*)d_out;

    const int SMEM_BUILD = (CS * DV + CS * D) * 4;                        // 81920 B
    const int SMEM_MAIN  = (CS * DV + S_FLOATS + CS * D + CS * 17) * 4;   // 139104 B

    cudaFuncSetAttribute(build_kernel, cudaFuncAttributeMaxDynamicSharedMemorySize, SMEM_BUILD);
    cudaFuncSetAttribute(main_kernel,  cudaFuncAttributeMaxDynamicSharedMemorySize, SMEM_MAIN);

    build_kernel<<<NCHUNK, 256, SMEM_BUILD>>>(k, v);
    prefix_kernel<<<dim3(BH, 4), 256>>>();
    main_kernel<<<NCHUNK, 256, SMEM_MAIN>>>(q, k, v, out);
}

// round 6
// speedup vs baseline: 1.3325x; 1.3325x over previous
#include <cuda_runtime.h>
#include <cstdint>

#define D       16
#define DV      64
#define CS      256
#define NCHUNK  512
#define NPAIR   136

#define OFF_KSUM  0
#define OFF_K2    16
#define OFF_VSUM  152
#define OFF_KVLIN 216
#define OFF_KVQ   1240
#define S_FLOATS  9944

__device__ __align__(16) float g_state[(size_t)NCHUNK * S_FLOATS];

__device__ __forceinline__ uint32_t f2tf(float f) {
    uint32_t r; asm("cvt.rna.tf32.f32 %0, %1;" : "=r"(r) : "f"(f)); return r;
}
__device__ __forceinline__ void mma8(float* c, const uint32_t* a, const uint32_t* b) {
    asm volatile("mma.sync.aligned.m16n8k8.row.col.f32.tf32.tf32.f32 "
        "{%0,%1,%2,%3}, {%4,%5,%6,%7}, {%8,%9}, {%0,%1,%2,%3};"
        : "+f"(c[0]), "+f"(c[1]), "+f"(c[2]), "+f"(c[3])
        : "r"(a[0]), "r"(a[1]), "r"(a[2]), "r"(a[3]), "r"(b[0]), "r"(b[1]));
}

__device__ __forceinline__ void st_state(float* st, int p, int n, float v) {
    if (n < 64) {
        if (p < 136)      st[OFF_KVQ + p * 64 + n] = v;
        else if (p < 152) st[OFF_KVLIN + (p - 136) * 64 + n] = v;
        else if (p == 152) st[OFF_VSUM + n] = v;
    } else if (n == 64) {
        if (p < 136)      st[OFF_K2 + p] = v;
        else if (p < 152) st[OFF_KSUM + (p - 136)] = v;
    }
}

// ===========================================================================
// Pass 1: per-chunk states. G[160x72] = A[160x256] * [V | 1], A on the fly.
// A rows: 0..135 = w*k_d*k_e (w=0.5 diag), 136..151 = k_d, 152 = 1, 153..159 = 0.
// ===========================================================================
#define B_SK   0                    // 256*17 f32
#define B_SV   17408                // 256*72 u32 (tf32)
#define B_TDE  91136                // 160 u32
#define B_TW   91776                // 160 f32
#define B_SMEM 92416

__global__ __launch_bounds__(256) void build_kernel(const float* __restrict__ kg,
                                                    const float* __restrict__ vg) {
    extern __shared__ __align__(16) char smem[];
    float*    skf  = (float*)(smem + B_SK);
    uint32_t* svu  = (uint32_t*)(smem + B_SV);
    uint32_t* tde  = (uint32_t*)(smem + B_TDE);
    float*    tw   = (float*)(smem + B_TW);
    const int cg = blockIdx.x, tid = threadIdx.x;
    const int w = tid >> 5, lane = tid & 31, gid = lane >> 2, tig = lane & 3;

    const float* kc = kg + (size_t)cg * CS * D;
    const float* vc = vg + (size_t)cg * CS * DV;

    for (int idx = tid; idx < 256 * 16; idx += 256)
        skf[(idx >> 4) * 17 + (idx & 15)] = kc[idx];
    skf[tid * 17 + 16] = 1.0f;
    for (int idx = tid; idx < 256 * 64; idx += 256)
        svu[(idx >> 6) * 72 + (idx & 63)] = f2tf(vc[idx]);
    for (int idx = tid; idx < 256 * 8; idx += 256)
        svu[(idx >> 3) * 72 + 64 + (idx & 7)] = ((idx & 7) == 0) ? 0x3f800000u : 0u;
    if (tid < 160) {
        int d, e;
        if (tid < NPAIR) {
            int dd = 0, pp = tid;
            while (pp >= D - dd) { pp -= (D - dd); ++dd; }
            d = dd; e = dd + pp;
        } else if (tid < 152) { d = tid - 136; e = 16; }
        else { d = 16; e = 16; }
        tde[tid] = (uint32_t)((d << 8) | e);
        tw[tid] = (tid < NPAIR) ? ((tde[tid] >> 8) == (tde[tid] & 255) ? 0.5f : 1.0f)
                                : ((tid < 153) ? 1.0f : 0.0f);
    }
    __syncthreads();

    float* st = g_state + (size_t)cg * S_FLOATS;
    for (int mt = w; mt < 10; mt += 8) {
        const int r0 = mt * 16 + gid, r1 = r0 + 8;
        const uint32_t t0 = tde[r0], t1 = tde[r1];
        const int d0 = t0 >> 8, e0 = t0 & 255, d1 = t1 >> 8, e1 = t1 & 255;
        const float w0 = tw[r0], w1 = tw[r1];

        float c9[9][4];
#pragma unroll
        for (int nt = 0; nt < 9; ++nt)
#pragma unroll
            for (int i = 0; i < 4; ++i) c9[nt][i] = 0.f;

        for (int ks = 0; ks < 32; ++ks) {
            const float* kA = skf + (ks * 8 + tig) * 17;
            const float* kB = kA + 4 * 17;
            uint32_t a[4];
            a[0] = f2tf(w0 * kA[d0] * kA[e0]);
            a[1] = f2tf(w1 * kA[d1] * kA[e1]);
            a[2] = f2tf(w0 * kB[d0] * kB[e0]);
            a[3] = f2tf(w1 * kB[d1] * kB[e1]);
            const uint32_t* bv0 = svu + (ks * 8 + tig) * 72 + gid;
            const uint32_t* bv1 = bv0 + 4 * 72;
#pragma unroll
            for (int nt = 0; nt < 9; ++nt) {
                uint32_t b[2] = { bv0[nt * 8], bv1[nt * 8] };
                mma8(c9[nt], a, b);
            }
        }
#pragma unroll
        for (int nt = 0; nt < 9; ++nt) {
            const int n0 = nt * 8 + 2 * tig;
            st_state(st, r0, n0,     c9[nt][0]);
            st_state(st, r0, n0 + 1, c9[nt][1]);
            st_state(st, r1, n0,     c9[nt][2]);
            st_state(st, r1, n0 + 1, c9[nt][3]);
        }
    }
}

// ===========================================================================
// Pass 2: exclusive prefix over 16 chunks per (b,h).
// ===========================================================================
__global__ void prefix_kernel() {
    const int bh = blockIdx.x;
    const int stride = gridDim.y * blockDim.x;
    for (int i = blockIdx.y * blockDim.x + threadIdx.x; i < S_FLOATS; i += stride) {
        float* p = g_state + (size_t)bh * 16 * S_FLOATS + i;
        float run = 0.f;
#pragma unroll
        for (int c = 0; c < 16; ++c) {
            const float t = p[(size_t)c * S_FLOATS];
            p[(size_t)c * S_FLOATS] = run;
            run += t;
        }
    }
}

// ===========================================================================
// Pass 3: half-chunk (M=128), 1024 CTAs x 8 warps.
// GEMM1: S = q K^T (C frags) -> phi + causal mask -> per-warp smem tile ->
// GEMM2: O[16x72] += phiS * Vblk  (+ extras: qpairs * state rows).
// z rides in output column 64 (ones col in V, k2/ksum/count in state).
// ===========================================================================
#define M_SQ   0                    // 128*17 f32
#define M_SK   8704                 // 256*17 u32 (tf32)
#define M_SV   26112                // 416*72 u32 (tf32)
#define M_ST   145920               // 128*132 u32 (phi-S tile, per-warp rows)
#define M_TDE  213504               // 160 u32
#define M_SMEM 214144

__global__ __launch_bounds__(256) void main_kernel(const float* __restrict__ qg,
                                                   const float* __restrict__ kg,
                                                   const float* __restrict__ vg,
                                                   float* __restrict__ outg) {
    extern __shared__ __align__(16) char smem[];
    float*    sq   = (float*)(smem + M_SQ);
    uint32_t* sku  = (uint32_t*)(smem + M_SK);
    uint32_t* svu  = (uint32_t*)(smem + M_SV);
    uint32_t* stile= (uint32_t*)(smem + M_ST);
    uint32_t* tde  = (uint32_t*)(smem + M_TDE);

    const int cg = blockIdx.x, chunk = cg >> 1, half = cg & 1, nc = chunk & 15;
    const int tid = threadIdx.x;
    const int w = tid >> 5, lane = tid & 31, gid = lane >> 2, tig = lane & 3;

    const float* qc = qg + (size_t)chunk * CS * D + (size_t)half * 128 * D;
    const float* kc = kg + (size_t)chunk * CS * D;
    const float* vc = vg + (size_t)chunk * CS * DV;
    const float* st = g_state + (size_t)chunk * S_FLOATS;

    // ---- fills ----
    for (int idx = tid; idx < 128 * 16; idx += 256)
        sq[(idx >> 4) * 17 + (idx & 15)] = 0.25f * qc[idx];
    if (tid < 128) sq[tid * 17 + 16] = 1.0f;
    for (int idx = tid; idx < 256 * 16; idx += 256)
        sku[(idx >> 4) * 17 + (idx & 15)] = f2tf(kc[idx]);
    const int vrows = half ? 256 : 128;
    for (int idx = tid; idx < vrows * 64; idx += 256)
        svu[(idx >> 6) * 72 + (idx & 63)] = f2tf(vc[idx]);
    for (int idx = tid; idx < vrows * 8; idx += 256)
        svu[(idx >> 3) * 72 + 64 + (idx & 7)] = ((idx & 7) == 0) ? 0x3f800000u : 0u;
    for (int idx = tid; idx < 160 * 72; idx += 256) {
        const int i = idx / 72, n = idx - i * 72;
        float v;
        if (n < 64) {
            if (i < NPAIR)      v = st[OFF_KVQ + i * 64 + n];
            else if (i < 152)   v = st[OFF_KVLIN + (i - 136) * 64 + n];
            else if (i == 152)  v = st[OFF_VSUM + n];
            else v = 0.f;
        } else if (n == 64) {
            if (i < NPAIR)      v = st[OFF_K2 + i];
            else if (i < 152)   v = st[OFF_KSUM + (i - 136)];
            else if (i == 152)  v = (float)(nc * CS);
            else v = 0.f;
        } else v = 0.f;
        svu[(256 + i) * 72 + n] = f2tf(v);
    }
    if (tid < 160) {
        int d, e;
        if (tid < NPAIR) {
            int dd = 0, pp = tid;
            while (pp >= D - dd) { pp -= (D - dd); ++dd; }
            d = dd; e = dd + pp;
        } else if (tid < 152) { d = tid - 136; e = 16; }
        else { d = 16; e = 16; }
        tde[tid] = (uint32_t)((d << 8) | e);
    }
    __syncthreads();

    // ---- per-warp: rows r0 = w*16+gid, r1 = r0+8 (local to half) ----
    const int rl0 = w * 16 + gid, rl1 = rl0 + 8;
    const int rg0 = half * 128 + rl0, rg1 = rg0 + 8;      // row within chunk
    const float* qr0 = sq + rl0 * 17;
    const float* qr1 = sq + rl1 * 17;

    uint32_t aS[2][4];
#pragma unroll
    for (int ks = 0; ks < 2; ++ks) {
        aS[ks][0] = f2tf(qr0[ks * 8 + tig]);
        aS[ks][1] = f2tf(qr1[ks * 8 + tig]);
        aS[ks][2] = f2tf(qr0[ks * 8 + tig + 4]);
        aS[ks][3] = f2tf(qr1[ks * 8 + tig + 4]);
    }

    float oc[9][4];
#pragma unroll
    for (int nt = 0; nt < 9; ++nt)
#pragma unroll
        for (int i = 0; i < 4; ++i) oc[nt][i] = 0.f;

    for (int jb = 0; jb <= half; ++jb) {
        const int jbase = jb * 128;
        // --- GEMM1 strip + phi + mask -> stile ---
        for (int nt = 0; nt < 16; ++nt) {
            const int j0 = jbase + nt * 8 + gid;
            float c4[4] = {0.f, 0.f, 0.f, 0.f};
#pragma unroll
            for (int ks = 0; ks < 2; ++ks) {
                uint32_t b[2] = { sku[j0 * 17 + ks * 8 + tig],
                                  sku[j0 * 17 + ks * 8 + tig + 4] };
                mma8(c4, aS[ks], b);
            }
            const int cg0 = jbase + nt * 8 + 2 * tig, cg1 = cg0 + 1;
            float p0 = fmaf(0.5f * c4[0], c4[0], c4[0]) + 1.0f;
            float p1 = fmaf(0.5f * c4[1], c4[1], c4[1]) + 1.0f;
            float p2 = fmaf(0.5f * c4[2], c4[2], c4[2]) + 1.0f;
            float p3 = fmaf(0.5f * c4[3], c4[3], c4[3]) + 1.0f;
            uint2 u0, u1;
            u0.x = (cg0 <= rg0) ? f2tf(p0) : 0u;
            u0.y = (cg1 <= rg0) ? f2tf(p1) : 0u;
            u1.x = (cg0 <= rg1) ? f2tf(p2) : 0u;
            u1.y = (cg1 <= rg1) ? f2tf(p3) : 0u;
            uint32_t* sp = stile + rl0 * 132 + nt * 8 + 2 * tig;
            *(uint2*)sp = u0;
            *(uint2*)(sp + 8 * 132) = u1;
        }
        __syncwarp();
        // --- GEMM2 accumulate over this jblock ---
        const uint32_t* srow0 = stile + rl0 * 132;
        for (int ks = 0; ks < 16; ++ks) {
            uint32_t a[4];
            a[0] = srow0[ks * 8 + tig];
            a[1] = srow0[8 * 132 + ks * 8 + tig];
            a[2] = srow0[ks * 8 + tig + 4];
            a[3] = srow0[8 * 132 + ks * 8 + tig + 4];
            const uint32_t* bv0 = svu + (jbase + ks * 8 + tig) * 72 + gid;
            const uint32_t* bv1 = bv0 + 4 * 72;
#pragma unroll
            for (int nt = 0; nt < 9; ++nt) {
                uint32_t b[2] = { bv0[nt * 8], bv1[nt * 8] };
                mma8(oc[nt], a, b);
            }
        }
        __syncwarp();
    }

    // --- extras: A cols 256..415 = [q_d*q_e | q | 1 | 0], B = state rows ---
    for (int ks = 0; ks < 20; ++ks) {
        const int i0 = ks * 8 + tig, i1 = i0 + 4;
        const uint32_t t0 = tde[i0], t1 = tde[i1];
        const float w0s = (i0 < 153) ? 1.f : 0.f;
        const float w1s = (i1 < 153) ? 1.f : 0.f;
        const int d0 = t0 >> 8, e0 = t0 & 255, d1 = t1 >> 8, e1 = t1 & 255;
        uint32_t a[4];
        a[0] = f2tf(w0s * qr0[d0] * qr0[e0]);
        a[1] = f2tf(w0s * qr1[d0] * qr1[e0]);
        a[2] = f2tf(w1s * qr0[d1] * qr0[e1]);
        a[3] = f2tf(w1s * qr1[d1] * qr1[e1]);
        const uint32_t* bv0 = svu + (256 + ks * 8 + tig) * 72 + gid;
        const uint32_t* bv1 = bv0 + 4 * 72;
#pragma unroll
        for (int nt = 0; nt < 9; ++nt) {
            uint32_t b[2] = { bv0[nt * 8], bv1[nt * 8] };
            mma8(oc[nt], a, b);
        }
    }

    // --- epilogue: z in col 64 (nt=8, tig==0 lanes), divide, store ---
    const float z0 = __shfl_sync(0xffffffffu, oc[8][0], lane & 28);
    const float z1 = __shfl_sync(0xffffffffu, oc[8][2], lane & 28);
    const float inv0 = 1.0f / (z0 + 1e-6f);
    const float inv1 = 1.0f / (z1 + 1e-6f);
    float2* o0 = (float2*)(outg + ((size_t)chunk * CS + rg0) * DV);
    float2* o1 = (float2*)(outg + ((size_t)chunk * CS + rg1) * DV);
#pragma unroll
    for (int nt = 0; nt < 8; ++nt) {
        float2 r0v, r1v;
        r0v.x = oc[nt][0] * inv0; r0v.y = oc[nt][1] * inv0;
        r1v.x = oc[nt][2] * inv1; r1v.y = oc[nt][3] * inv1;
        o0[nt * 4 + tig] = r0v;
        o1[nt * 4 + tig] = r1v;
    }
}

// ---------------------------------------------------------------------------
extern "C" void kernel_launch(void* const* d_in, const int* in_sizes, int n_in,
                              void* d_out, int out_size) {
    (void)in_sizes; (void)n_in; (void)out_size;
    const float* q = (const float*)d_in[0];
    const float* k = (const float*)d_in[1];
    const float* v = (const float*)d_in[2];
    float* out = (float*)d_out;

    cudaFuncSetAttribute(build_kernel, cudaFuncAttributeMaxDynamicSharedMemorySize, B_SMEM);
    cudaFuncSetAttribute(main_kernel,  cudaFuncAttributeMaxDynamicSharedMemorySize, M_SMEM);

    build_kernel<<<NCHUNK, 256, B_SMEM>>>(k, v);
    prefix_kernel<<<dim3(32, 4), 256>>>();
    main_kernel<<<NCHUNK * 2, 256, M_SMEM>>>(q, k, v, out);
}